// round 8
// baseline (speedup 1.0000x reference)
#include <cuda_runtime.h>
#include <cuda_bf16.h>
#include <mma.h>
#include <cstdint>
#include <math.h>

using namespace nvcuda;

#define NE     100000
#define NEDGE  500000
#define NREL2  474
#define NTEST  131072
#define KCAT   880      /* 875 padded to multiple of 16 */

// ---------------- scratch (static device globals; no allocation) ----------------
__device__ float          g_aggpre[(size_t)NE * 200];
__device__ float          g_deg[NE];
__device__ __nv_bfloat16  g_X[(size_t)NE * 400];
__device__ __nv_bfloat16  g_allent[(size_t)NE * 200];
__device__ __nv_bfloat16  g_cat[(size_t)NTEST * KCAT];
__device__ __nv_bfloat16  g_HT[(size_t)NTEST * 200];
__device__ float          g_QK[(size_t)NTEST * 256];
__device__ __nv_bfloat16  g_H1[(size_t)NTEST * 2048];
__device__ __nv_bfloat16  g_H2[(size_t)NTEST * 512];
__device__ float          g_allrel[474 * 200];
__device__ __nv_bfloat16  g_Wcat[400 * 200];
__device__ __nv_bfloat16  g_T2[400 * 200];
__device__ __nv_bfloat16  g_QKw[200 * 256];
__device__ __nv_bfloat16  g_Brel[200 * 480];   /* ldb padded 474 -> 480 for 16B align */
__device__ __nv_bfloat16  g_w1b[880 * 2048];
__device__ __nv_bfloat16  g_w2b[2048 * 512];
__device__ float          g_bias2[200];
__device__ float          g_biasQK[256];

// ---------------- small kernels ----------------
__global__ void k_zero() {
    size_t gid = (size_t)blockIdx.x * blockDim.x + threadIdx.x;
    const size_t n1 = (size_t)NE * 200 / 4;   // aggpre float4 count
    const size_t n2 = NE / 4;                 // deg float4 count
    float4 z = make_float4(0.f, 0.f, 0.f, 0.f);
    if (gid < n1)            ((float4*)g_aggpre)[gid] = z;
    else if (gid < n1 + n2)  ((float4*)g_deg)[gid - n1] = z;
}

__global__ void k_scatter(const int* __restrict__ ei, const int* __restrict__ et,
                          const float* __restrict__ ent, const float* __restrict__ rel) {
    int gid = blockIdx.x * blockDim.x + threadIdx.x;
    if (gid >= NEDGE * 50) return;
    int e = gid / 50, c = (gid % 50) * 4;
    int s = ei[e], d = ei[NEDGE + e], t = et[e];
    float4 a = *(const float4*)(ent + (size_t)s * 200 + c);
    float4 r = *(const float4*)(rel + (size_t)t * 200 + c);
    float* o = g_aggpre + (size_t)d * 200 + c;
    atomicAdd(o + 0, a.x - r.x);
    atomicAdd(o + 1, a.y - r.y);
    atomicAdd(o + 2, a.z - r.z);
    atomicAdd(o + 3, a.w - r.w);
    if (c == 0) atomicAdd(g_deg + d, 1.0f);
}

__global__ void k_buildX(const float* __restrict__ ent) {
    int gid = blockIdx.x * blockDim.x + threadIdx.x;
    if (gid >= NE * 200) return;
    int i = gid / 200, c = gid % 200;
    float nrm = rsqrtf(fmaxf(g_deg[i], 1.0f));
    g_X[(size_t)i * 400 + c]       = __float2bfloat16(g_aggpre[gid] * nrm);
    g_X[(size_t)i * 400 + 200 + c] = __float2bfloat16(ent[gid]);
}

__global__ void k_f2b(__nv_bfloat16* __restrict__ dst, const float* __restrict__ src, int n) {
    int gid = blockIdx.x * blockDim.x + threadIdx.x;
    if (gid < n) dst[gid] = __float2bfloat16(src[gid]);
}

__global__ void k_w1b(const float* __restrict__ w1) {  // 880 x 2048, rows >=875 zero
    int gid = blockIdx.x * blockDim.x + threadIdx.x;
    if (gid >= 880 * 2048) return;
    int r = gid / 2048;
    g_w1b[gid] = __float2bfloat16(r < 875 ? w1[gid] : 0.0f);
}

__global__ void k_T2(const float* __restrict__ tw) {   // 400 x 200 block-diag trans_w
    int gid = blockIdx.x * blockDim.x + threadIdx.x;
    if (gid >= 400 * 200) return;
    int r = gid / 200, c = gid % 200;
    float v = 0.f;
    if (r < 200)  { if (c < 100)  v = tw[r * 100 + c]; }
    else          { if (c >= 100) v = tw[(r - 200) * 100 + (c - 100)]; }
    g_T2[gid] = __float2bfloat16(v);
}

__global__ void k_QKw(const float* __restrict__ qw, const float* __restrict__ kw) { // 200 x 256
    int gid = blockIdx.x * blockDim.x + threadIdx.x;
    if (gid >= 200 * 256) return;
    int r = gid / 256, c = gid % 256;
    float v = 0.f;
    if (r < 100 && c < 128)   v = qw[r * 128 + c];
    if (r >= 100 && c >= 128) v = kw[(r - 100) * 128 + (c - 128)];
    g_QKw[gid] = __float2bfloat16(v);
}

__global__ void k_bias(const float* __restrict__ tb, const float* __restrict__ qb,
                       const float* __restrict__ kb) {
    int gid = blockIdx.x * blockDim.x + threadIdx.x;
    if (gid < 200) g_bias2[gid] = tb[gid % 100];
    else if (gid < 456) {
        int c = gid - 200;
        g_biasQK[c] = (c < 128) ? qb[c] : kb[c - 128];
    }
}

__global__ void k_allrel(const float* __restrict__ rel, const float* __restrict__ Wr) {
    __shared__ float rr[200];
    int r = blockIdx.x;  // 474 blocks
    if (threadIdx.x < 200) rr[threadIdx.x] = rel[(size_t)r * 200 + threadIdx.x];
    __syncthreads();
    int c = threadIdx.x;
    if (c < 200) {
        float s = 0.f;
        #pragma unroll 8
        for (int k = 0; k < 200; k++) s += rr[k] * Wr[(size_t)k * 200 + c];
        g_allrel[(size_t)r * 200 + c] = s;
    }
}

__global__ void k_brel() {   // Brel[k, r] = (k<100 ? +1 : -1) * allrel[r, k], ld 480
    int gid = blockIdx.x * blockDim.x + threadIdx.x;
    if (gid >= 200 * 480) return;
    int k = gid / 480, r = gid % 480;
    float v = 0.f;
    if (r < NREL2) v = (k < 100 ? 1.f : -1.f) * g_allrel[r * 200 + k];
    g_Brel[gid] = __float2bfloat16(v);
}

__global__ void k_gather(const int* __restrict__ tt) {
    int gid = blockIdx.x * blockDim.x + threadIdx.x;  // NTEST*64
    int i = gid >> 6, q = gid & 63;
    if (i >= NTEST) return;
    if (q < 50) {
        int which = q / 25, qq = q % 25;
        int node = tt[i * 2 + which];
        const uint4* src = (const uint4*)(g_allent + (size_t)node * 200) + qq;
        uint4* dst = (uint4*)(g_cat + (size_t)i * KCAT + which * 200) + qq;
        *dst = *src;
    } else if (q < 55) {
        g_cat[(size_t)i * KCAT + 875 + (q - 50)] = __float2bfloat16(0.f);  // K pad
    }
}

__global__ void k_atta() {
    int g = blockIdx.x * blockDim.x + threadIdx.x;
    int w = g >> 5, lane = g & 31;
    if (w >= NTEST) return;
    const float* q = g_QK + (size_t)w * 256;
    float s = q[lane]      * q[128 + lane]
            + q[32 + lane] * q[160 + lane]
            + q[64 + lane] * q[192 + lane]
            + q[96 + lane] * q[224 + lane];
    #pragma unroll
    for (int o = 16; o; o >>= 1) s += __shfl_xor_sync(0xffffffffu, s, o);
    if (lane == 0)
        g_cat[(size_t)w * KCAT + 400] = __float2bfloat16(s * 0.07071067811865475f); // 1/sqrt(200)
}

__global__ void k_final(const float* __restrict__ w3, const float* __restrict__ b3,
                        float* __restrict__ out) {
    int g = blockIdx.x * blockDim.x + threadIdx.x;
    int w = g >> 5, lane = g & 31;
    if (w >= NTEST) return;
    const __nv_bfloat162* h = (const __nv_bfloat162*)(g_H2 + (size_t)w * 512);
    const float2* w32 = (const float2*)w3;
    float s = 0.f;
    #pragma unroll
    for (int j = 0; j < 8; j++) {
        int p = lane + 32 * j;
        __nv_bfloat162 hv = h[p];
        float2 wv = w32[p];
        s += __bfloat162float(hv.x) * wv.x + __bfloat162float(hv.y) * wv.y;
    }
    #pragma unroll
    for (int o = 16; o; o >>= 1) s += __shfl_xor_sync(0xffffffffu, s, o);
    if (lane == 0) out[w] = 1.f / (1.f + expf(-(s + b3[0])));
}

// ---------------- generic bf16 WMMA GEMM: C = act(A @ B + bias) ----------------
__device__ __forceinline__ void cp16(void* sm, const void* g, int sz) {
    unsigned s = (unsigned)__cvta_generic_to_shared(sm);
    asm volatile("cp.async.cg.shared.global [%0], [%1], 16, %2;\n" :: "r"(s), "l"(g), "r"(sz));
}

// ACT: 0 none, 1 tanh, 2 lrelu 1e-4, 3 lrelu 1e-3
template<int ACT, typename CT>
__global__ void __launch_bounds__(256)
k_gemm(const __nv_bfloat16* __restrict__ A, int lda,
       const __nv_bfloat16* __restrict__ B, int ldb,
       CT* __restrict__ C, int ldc, int ccol0,
       const float* __restrict__ bias,
       int M, int N, int K)
{
    constexpr int BM = 128, BN = 128, BK = 16, LDB_S = BN + 8, LDC_S = 36;
    __shared__ __nv_bfloat16 sA[2][BM * BK];
    __shared__ __nv_bfloat16 sB[2][BK * LDB_S];
    __shared__ float sC[8][16 * LDC_S];

    int tid = threadIdx.x;
    int warp = tid >> 5, lane = tid & 31;
    int wm = warp & 1, wn = warp >> 1;            // 2x4 warp grid: 64-row x 32-col tiles
    int bm0 = blockIdx.x * BM, bn0 = blockIdx.y * BN;

    // A tile loads: 128 rows x 16 cols, 8 bf16 (16B) per thread
    int arow = tid >> 1;
    int akoff = (tid & 1) << 3;
    int arow_g = bm0 + arow;
    int asz = (arow_g < M) ? 16 : 0;
    const __nv_bfloat16* aptr = A + (size_t)min(arow_g, M - 1) * lda + akoff;

    // B tile loads: 16 rows x 128 cols, 8 bf16 per thread (with zero-fill at N edge)
    int brow = tid >> 4;
    int bcoff = (tid & 15) << 3;
    int bcol = bn0 + bcoff;
    int bsz = N - bcol; bsz = bsz < 0 ? 0 : (bsz > 8 ? 8 : bsz); bsz *= 2;
    const __nv_bfloat16* bptr = B + (size_t)brow * ldb + (bsz ? bcol : 0);

    wmma::fragment<wmma::accumulator, 16, 16, 16, float> acc[4][2];
    #pragma unroll
    for (int i = 0; i < 4; i++)
        #pragma unroll
        for (int j = 0; j < 2; j++) wmma::fill_fragment(acc[i][j], 0.0f);

    __nv_bfloat16* saw = &sA[0][arow * BK + akoff];
    __nv_bfloat16* sbw = &sB[0][brow * LDB_S + bcoff];
    const int offA = BM * BK, offB = BK * LDB_S;

    int KT = K / BK;
    cp16(saw, aptr, asz);
    cp16(sbw, bptr, bsz);
    asm volatile("cp.async.commit_group;\n");

    for (int kt = 0; kt < KT; ++kt) {
        asm volatile("cp.async.wait_group 0;\n");
        __syncthreads();
        int buf = kt & 1;
        if (kt + 1 < KT) {
            int nb = buf ^ 1;
            cp16(saw + nb * offA, aptr + (size_t)(kt + 1) * BK, asz);
            cp16(sbw + nb * offB, bptr + (size_t)(kt + 1) * BK * ldb, bsz);
            asm volatile("cp.async.commit_group;\n");
        }
        wmma::fragment<wmma::matrix_b, 16, 16, 16, __nv_bfloat16, wmma::row_major> fb[2];
        #pragma unroll
        for (int j = 0; j < 2; j++)
            wmma::load_matrix_sync(fb[j], &sB[buf][wn * 32 + j * 16], LDB_S);
        #pragma unroll
        for (int i = 0; i < 4; i++) {
            wmma::fragment<wmma::matrix_a, 16, 16, 16, __nv_bfloat16, wmma::row_major> fa;
            wmma::load_matrix_sync(fa, &sA[buf][(wm * 64 + i * 16) * BK], BK);
            #pragma unroll
            for (int j = 0; j < 2; j++)
                wmma::mma_sync(acc[i][j], fa, fb[j], acc[i][j]);
        }
    }

    // epilogue: per-warp smem staging, scalar guarded writes with fused bias+act
    float* sc = sC[warp];
    int r = lane >> 1;
    int cb = (lane & 1) << 4;
    #pragma unroll
    for (int i = 0; i < 4; i++) {
        wmma::store_matrix_sync(sc,      acc[i][0], LDC_S, wmma::mem_row_major);
        wmma::store_matrix_sync(sc + 16, acc[i][1], LDC_S, wmma::mem_row_major);
        __syncwarp();
        int row = bm0 + wm * 64 + i * 16 + r;
        if (row < M) {
            CT* cout = C + (size_t)row * ldc + ccol0;
            int col0 = bn0 + wn * 32 + cb;
            #pragma unroll
            for (int c = 0; c < 16; c++) {
                int col = col0 + c;
                if (col < N) {
                    float v = sc[r * LDC_S + cb + c];
                    if (bias) v += bias[col];
                    if (ACT == 1) v = tanhf(v);
                    else if (ACT == 2) v = v >= 0.f ? v : 1e-4f * v;
                    else if (ACT == 3) v = v >= 0.f ? v : 1e-3f * v;
                    if constexpr (sizeof(CT) == 2) cout[col] = __float2bfloat16(v);
                    else                           cout[col] = v;
                }
            }
        }
        __syncwarp();
    }
}

// ---------------- launch ----------------
extern "C" void kernel_launch(void* const* d_in, const int* in_sizes, int n_in,
                              void* d_out, int out_size) {
    const int *ei = 0, *et = 0, *tt = 0;
    const float *ent = 0, *rel = 0, *W = 0, *Wl = 0, *Wr = 0, *tw = 0, *tb = 0;
    const float *qw = 0, *qb = 0, *kw = 0, *kb = 0, *w1 = 0, *b1 = 0, *w2 = 0, *b2 = 0, *w3 = 0, *b3 = 0;
    int c40 = 0, c12800 = 0, c128 = 0, c512 = 0;
    for (int i = 0; i < n_in; i++) {
        const void* p = d_in[i];
        switch (in_sizes[i]) {
            case 1000000:  ei = (const int*)p; break;
            case 500000:   et = (const int*)p; break;
            case 262144:   tt = (const int*)p; break;
            case 20000000: ent = (const float*)p; break;
            case 94800:    rel = (const float*)p; break;
            case 40000:    if (c40 == 0) W = (const float*)p;
                           else if (c40 == 1) Wl = (const float*)p;
                           else Wr = (const float*)p;
                           c40++; break;
            case 20000:    tw = (const float*)p; break;
            case 100:      tb = (const float*)p; break;
            case 12800:    if (c12800 == 0) qw = (const float*)p; else kw = (const float*)p;
                           c12800++; break;
            case 128:      if (c128 == 0) qb = (const float*)p; else kb = (const float*)p;
                           c128++; break;
            case 1792000:  w1 = (const float*)p; break;
            case 2048:     b1 = (const float*)p; break;
            case 1048576:  w2 = (const float*)p; break;
            case 512:      if (c512 == 0) b2 = (const float*)p; else w3 = (const float*)p;
                           c512++; break;
            case 1:        b3 = (const float*)p; break;
        }
    }
    if (!ei || !et || !tt || !ent || !rel || !W || !Wl || !Wr || !tw || !tb ||
        !qw || !qb || !kw || !kb || !w1 || !b1 || !w2 || !b2 || !w3 || !b3) return;

    void *vX, *vWcat, *vAllent, *vCat, *vT2, *vHT, *vQKw, *vQK, *vBrel, *vW1b, *vH1, *vW2b, *vH2, *vB2, *vBQK;
    cudaGetSymbolAddress(&vX, g_X);
    cudaGetSymbolAddress(&vWcat, g_Wcat);
    cudaGetSymbolAddress(&vAllent, g_allent);
    cudaGetSymbolAddress(&vCat, g_cat);
    cudaGetSymbolAddress(&vT2, g_T2);
    cudaGetSymbolAddress(&vHT, g_HT);
    cudaGetSymbolAddress(&vQKw, g_QKw);
    cudaGetSymbolAddress(&vQK, g_QK);
    cudaGetSymbolAddress(&vBrel, g_Brel);
    cudaGetSymbolAddress(&vW1b, g_w1b);
    cudaGetSymbolAddress(&vH1, g_H1);
    cudaGetSymbolAddress(&vW2b, g_w2b);
    cudaGetSymbolAddress(&vH2, g_H2);
    cudaGetSymbolAddress(&vB2, g_bias2);
    cudaGetSymbolAddress(&vBQK, g_biasQK);

    __nv_bfloat16* X      = (__nv_bfloat16*)vX;
    __nv_bfloat16* WCAT   = (__nv_bfloat16*)vWcat;
    __nv_bfloat16* ALLENT = (__nv_bfloat16*)vAllent;
    __nv_bfloat16* CAT    = (__nv_bfloat16*)vCat;
    __nv_bfloat16* T2     = (__nv_bfloat16*)vT2;
    __nv_bfloat16* HT     = (__nv_bfloat16*)vHT;
    __nv_bfloat16* QKW    = (__nv_bfloat16*)vQKw;
    float*         QK     = (float*)vQK;
    __nv_bfloat16* BREL   = (__nv_bfloat16*)vBrel;
    __nv_bfloat16* W1B    = (__nv_bfloat16*)vW1b;
    __nv_bfloat16* H1     = (__nv_bfloat16*)vH1;
    __nv_bfloat16* W2B    = (__nv_bfloat16*)vW2b;
    __nv_bfloat16* H2     = (__nv_bfloat16*)vH2;
    float*         BIAS2  = (float*)vB2;
    float*         BIASQK = (float*)vBQK;

    const int T = 256;
    // 1) zero accumulators + degree
    k_zero<<<(5025000 + T - 1) / T, T>>>();
    // 2) edge scatter (segment sums hoisted out of the message GEMM)
    k_scatter<<<(NEDGE * 50 + T - 1) / T, T>>>(ei, et, ent, rel);
    // 3) weight prep (independent small kernels)
    k_f2b<<<(40000 + T - 1) / T, T>>>(WCAT, W, 40000);
    k_f2b<<<(40000 + T - 1) / T, T>>>(WCAT + 40000, Wl, 40000);
    k_f2b<<<(1048576 + T - 1) / T, T>>>(W2B, w2, 1048576);
    k_w1b<<<(880 * 2048 + T - 1) / T, T>>>(w1);
    k_T2<<<(400 * 200 + T - 1) / T, T>>>(tw);
    k_QKw<<<(200 * 256 + T - 1) / T, T>>>(qw, kw);
    k_bias<<<2, T>>>(tb, qb, kb);
    k_allrel<<<474, T>>>(rel, Wr);
    k_brel<<<(200 * 480 + T - 1) / T, T>>>();
    // 4) X = [agg*norm | ent] bf16
    k_buildX<<<(NE * 200 + T - 1) / T, T>>>(ent);
    // 5) all_ent = tanh(X @ [W;W_loop])       M=100000 N=200 K=400
    k_gemm<1, __nv_bfloat16><<<dim3(782, 2), T>>>(X, 400, WCAT, 200, ALLENT, 200, 0,
                                                  nullptr, NE, 200, 400);
    // 6) gather te pairs into cat[:, 0:400] (+ zero K-pad cols 875..879)
    k_gather<<<(NTEST * 64) / T, T>>>(tt);
    // 7) HT = [h_e|t_e] = cat[:,0:400] @ blockdiag(trans_w) + [tb|tb]   N=200 K=400
    k_gemm<0, __nv_bfloat16><<<dim3(1024, 2), T>>>(CAT, KCAT, T2, 200, HT, 200, 0,
                                                   BIAS2, NTEST, 200, 400);
    // 8) QK = HT @ blockdiag(q_w,k_w) + [q_b|k_b]   N=256 K=200 (fp32 out)
    k_gemm<0, float><<<dim3(1024, 2), T>>>(HT, 200, QKW, 256, QK, 256, 0,
                                           BIASQK, NTEST, 256, 200);
    // 9) atta -> cat[:, 400]
    k_atta<<<(NTEST * 32) / T, T>>>();
    // 10) relSim = HT @ [head_rel^T; -tail_rel^T] -> cat[:, 401:875]   N=474 K=200
    k_gemm<0, __nv_bfloat16><<<dim3(1024, 4), T>>>(HT, 200, BREL, 480, CAT, KCAT, 401,
                                                   nullptr, NTEST, NREL2, 200);
    // 11) H1 = lrelu(cat @ w1 + b1, 1e-4)      N=2048 K=880
    k_gemm<2, __nv_bfloat16><<<dim3(1024, 16), T>>>(CAT, KCAT, W1B, 2048, H1, 2048, 0,
                                                    b1, NTEST, 2048, 880);
    // 12) H2 = lrelu(H1 @ w2 + b2, 1e-3)       N=512 K=2048
    k_gemm<3, __nv_bfloat16><<<dim3(1024, 4), T>>>(H1, 2048, W2B, 512, H2, 512, 0,
                                                   b2, NTEST, 512, 2048);
    // 13) out = sigmoid(H2 @ w3 + b3)
    k_final<<<(NTEST * 32) / T, T>>>(w3, b3, (float*)d_out);
}

// round 9
// speedup vs baseline: 1.0113x; 1.0113x over previous
#include <cuda_runtime.h>
#include <cuda_bf16.h>
#include <mma.h>
#include <cstdint>
#include <math.h>

using namespace nvcuda;

#define NE     100000
#define NEDGE  500000
#define NREL2  474
#define NTEST  131072
#define KCAT   880      /* 875 padded to multiple of 16 */

// ---------------- scratch (static device globals; no allocation) ----------------
__device__ float          g_aggpre[(size_t)NE * 200];
__device__ float          g_deg[NE];
__device__ __nv_bfloat16  g_X[(size_t)NE * 400];
__device__ __nv_bfloat16  g_allent[(size_t)NE * 200];
__device__ __nv_bfloat16  g_cat[(size_t)NTEST * KCAT];
__device__ __nv_bfloat16  g_HT[(size_t)NTEST * 200];
__device__ float          g_QK[(size_t)NTEST * 256];
__device__ __nv_bfloat16  g_H1[(size_t)NTEST * 2048];
__device__ __nv_bfloat16  g_H2[(size_t)NTEST * 512];
__device__ float          g_allrel[474 * 200];
__device__ __nv_bfloat16  g_Wcat[400 * 200];
__device__ __nv_bfloat16  g_T2[400 * 200];
__device__ __nv_bfloat16  g_QKw[200 * 256];
__device__ __nv_bfloat16  g_Brel[200 * 480];   /* ldb padded 474 -> 480 for 16B align */
__device__ __nv_bfloat16  g_w1b[880 * 2048];
__device__ __nv_bfloat16  g_w2b[2048 * 512];
__device__ float          g_bias2[200];
__device__ float          g_biasQK[256];

// ---------------- small kernels ----------------
__global__ void k_zero() {
    size_t gid = (size_t)blockIdx.x * blockDim.x + threadIdx.x;
    const size_t n1 = (size_t)NE * 200 / 4;   // aggpre float4 count
    const size_t n2 = NE / 4;                 // deg float4 count
    float4 z = make_float4(0.f, 0.f, 0.f, 0.f);
    if (gid < n1)            ((float4*)g_aggpre)[gid] = z;
    else if (gid < n1 + n2)  ((float4*)g_deg)[gid - n1] = z;
}

__global__ void k_scatter(const int* __restrict__ ei, const int* __restrict__ et,
                          const float* __restrict__ ent, const float* __restrict__ rel) {
    int gid = blockIdx.x * blockDim.x + threadIdx.x;
    if (gid >= NEDGE * 50) return;
    int e = gid / 50, c = (gid % 50) * 4;
    int s = ei[e], d = ei[NEDGE + e], t = et[e];
    float4 a = *(const float4*)(ent + (size_t)s * 200 + c);
    float4 r = *(const float4*)(rel + (size_t)t * 200 + c);
    float* o = g_aggpre + (size_t)d * 200 + c;
    atomicAdd(o + 0, a.x - r.x);
    atomicAdd(o + 1, a.y - r.y);
    atomicAdd(o + 2, a.z - r.z);
    atomicAdd(o + 3, a.w - r.w);
    if (c == 0) atomicAdd(g_deg + d, 1.0f);
}

__global__ void k_buildX(const float* __restrict__ ent) {
    int gid = blockIdx.x * blockDim.x + threadIdx.x;
    if (gid >= NE * 200) return;
    int i = gid / 200, c = gid % 200;
    float nrm = rsqrtf(fmaxf(g_deg[i], 1.0f));
    g_X[(size_t)i * 400 + c]       = __float2bfloat16(g_aggpre[gid] * nrm);
    g_X[(size_t)i * 400 + 200 + c] = __float2bfloat16(ent[gid]);
}

__global__ void k_f2b(__nv_bfloat16* __restrict__ dst, const float* __restrict__ src, int n) {
    int gid = blockIdx.x * blockDim.x + threadIdx.x;
    if (gid < n) dst[gid] = __float2bfloat16(src[gid]);
}

__global__ void k_w1b(const float* __restrict__ w1) {  // 880 x 2048, rows >=875 zero
    int gid = blockIdx.x * blockDim.x + threadIdx.x;
    if (gid >= 880 * 2048) return;
    int r = gid / 2048;
    g_w1b[gid] = __float2bfloat16(r < 875 ? w1[gid] : 0.0f);
}

__global__ void k_T2(const float* __restrict__ tw) {   // 400 x 200 block-diag trans_w
    int gid = blockIdx.x * blockDim.x + threadIdx.x;
    if (gid >= 400 * 200) return;
    int r = gid / 200, c = gid % 200;
    float v = 0.f;
    if (r < 200)  { if (c < 100)  v = tw[r * 100 + c]; }
    else          { if (c >= 100) v = tw[(r - 200) * 100 + (c - 100)]; }
    g_T2[gid] = __float2bfloat16(v);
}

__global__ void k_QKw(const float* __restrict__ qw, const float* __restrict__ kw) { // 200 x 256
    int gid = blockIdx.x * blockDim.x + threadIdx.x;
    if (gid >= 200 * 256) return;
    int r = gid / 256, c = gid % 256;
    float v = 0.f;
    if (r < 100 && c < 128)   v = qw[r * 128 + c];
    if (r >= 100 && c >= 128) v = kw[(r - 100) * 128 + (c - 128)];
    g_QKw[gid] = __float2bfloat16(v);
}

__global__ void k_bias(const float* __restrict__ tb, const float* __restrict__ qb,
                       const float* __restrict__ kb) {
    int gid = blockIdx.x * blockDim.x + threadIdx.x;
    if (gid < 200) g_bias2[gid] = tb[gid % 100];
    else if (gid < 456) {
        int c = gid - 200;
        g_biasQK[c] = (c < 128) ? qb[c] : kb[c - 128];
    }
}

__global__ void k_allrel(const float* __restrict__ rel, const float* __restrict__ Wr) {
    __shared__ float rr[200];
    int r = blockIdx.x;  // 474 blocks
    if (threadIdx.x < 200) rr[threadIdx.x] = rel[(size_t)r * 200 + threadIdx.x];
    __syncthreads();
    int c = threadIdx.x;
    if (c < 200) {
        float s = 0.f;
        #pragma unroll 8
        for (int k = 0; k < 200; k++) s += rr[k] * Wr[(size_t)k * 200 + c];
        g_allrel[(size_t)r * 200 + c] = s;
    }
}

__global__ void k_brel() {   // Brel[k, r] = (k<100 ? +1 : -1) * allrel[r, k], ld 480
    int gid = blockIdx.x * blockDim.x + threadIdx.x;
    if (gid >= 200 * 480) return;
    int k = gid / 480, r = gid % 480;
    float v = 0.f;
    if (r < NREL2) v = (k < 100 ? 1.f : -1.f) * g_allrel[r * 200 + k];
    g_Brel[gid] = __float2bfloat16(v);
}

__global__ void k_gather(const int* __restrict__ tt) {
    int gid = blockIdx.x * blockDim.x + threadIdx.x;  // NTEST*64
    int i = gid >> 6, q = gid & 63;
    if (i >= NTEST) return;
    if (q < 50) {
        int which = q / 25, qq = q % 25;
        int node = tt[i * 2 + which];
        const uint4* src = (const uint4*)(g_allent + (size_t)node * 200) + qq;
        uint4* dst = (uint4*)(g_cat + (size_t)i * KCAT + which * 200) + qq;
        *dst = *src;
    } else if (q < 55) {
        g_cat[(size_t)i * KCAT + 875 + (q - 50)] = __float2bfloat16(0.f);  // K pad
    }
}

__global__ void k_atta() {
    int g = blockIdx.x * blockDim.x + threadIdx.x;
    int w = g >> 5, lane = g & 31;
    if (w >= NTEST) return;
    const float* q = g_QK + (size_t)w * 256;
    float s = q[lane]      * q[128 + lane]
            + q[32 + lane] * q[160 + lane]
            + q[64 + lane] * q[192 + lane]
            + q[96 + lane] * q[224 + lane];
    #pragma unroll
    for (int o = 16; o; o >>= 1) s += __shfl_xor_sync(0xffffffffu, s, o);
    if (lane == 0)
        g_cat[(size_t)w * KCAT + 400] = __float2bfloat16(s * 0.07071067811865475f); // 1/sqrt(200)
}

__global__ void k_final(const float* __restrict__ w3, const float* __restrict__ b3,
                        float* __restrict__ out) {
    int g = blockIdx.x * blockDim.x + threadIdx.x;
    int w = g >> 5, lane = g & 31;
    if (w >= NTEST) return;
    const __nv_bfloat162* h = (const __nv_bfloat162*)(g_H2 + (size_t)w * 512);
    const float2* w32 = (const float2*)w3;
    float s = 0.f;
    #pragma unroll
    for (int j = 0; j < 8; j++) {
        int p = lane + 32 * j;
        __nv_bfloat162 hv = h[p];
        float2 wv = w32[p];
        s += __bfloat162float(hv.x) * wv.x + __bfloat162float(hv.y) * wv.y;
    }
    #pragma unroll
    for (int o = 16; o; o >>= 1) s += __shfl_xor_sync(0xffffffffu, s, o);
    if (lane == 0) out[w] = 1.f / (1.f + expf(-(s + b3[0])));
}

// ---------------- generic bf16 WMMA GEMM: C = act(A @ B + bias) ----------------
__device__ __forceinline__ void cp16(void* sm, const void* g, int sz) {
    unsigned s = (unsigned)__cvta_generic_to_shared(sm);
    asm volatile("cp.async.cg.shared.global [%0], [%1], 16, %2;\n" :: "r"(s), "l"(g), "r"(sz));
}

// ACT: 0 none, 1 tanh, 2 lrelu 1e-4, 3 lrelu 1e-3
template<int ACT, typename CT>
__global__ void __launch_bounds__(256)
k_gemm(const __nv_bfloat16* __restrict__ A, int lda,
       const __nv_bfloat16* __restrict__ B, int ldb,
       CT* __restrict__ C, int ldc, int ccol0,
       const float* __restrict__ bias,
       int M, int N, int K)
{
    constexpr int BM = 128, BN = 128, BK = 16, LDB_S = BN + 8, LDC_S = 36;
    __shared__ __nv_bfloat16 sA[2][BM * BK];
    __shared__ __nv_bfloat16 sB[2][BK * LDB_S];
    __shared__ float sC[8][16 * LDC_S];

    int tid = threadIdx.x;
    int warp = tid >> 5, lane = tid & 31;
    int wm = warp & 1, wn = warp >> 1;            // 2x4 warp grid: 64-row x 32-col tiles
    int bm0 = blockIdx.x * BM, bn0 = blockIdx.y * BN;

    // A tile loads: 128 rows x 16 cols, 8 bf16 (16B) per thread
    int arow = tid >> 1;
    int akoff = (tid & 1) << 3;
    int arow_g = bm0 + arow;
    int asz = (arow_g < M) ? 16 : 0;
    const __nv_bfloat16* aptr = A + (size_t)min(arow_g, M - 1) * lda + akoff;

    // B tile loads: 16 rows x 128 cols, 8 bf16 per thread (with zero-fill at N edge)
    int brow = tid >> 4;
    int bcoff = (tid & 15) << 3;
    int bcol = bn0 + bcoff;
    int bsz = N - bcol; bsz = bsz < 0 ? 0 : (bsz > 8 ? 8 : bsz); bsz *= 2;
    const __nv_bfloat16* bptr = B + (size_t)brow * ldb + (bsz ? bcol : 0);

    wmma::fragment<wmma::accumulator, 16, 16, 16, float> acc[4][2];
    #pragma unroll
    for (int i = 0; i < 4; i++)
        #pragma unroll
        for (int j = 0; j < 2; j++) wmma::fill_fragment(acc[i][j], 0.0f);

    __nv_bfloat16* saw = &sA[0][arow * BK + akoff];
    __nv_bfloat16* sbw = &sB[0][brow * LDB_S + bcoff];
    const int offA = BM * BK, offB = BK * LDB_S;

    int KT = K / BK;
    cp16(saw, aptr, asz);
    cp16(sbw, bptr, bsz);
    asm volatile("cp.async.commit_group;\n");

    for (int kt = 0; kt < KT; ++kt) {
        asm volatile("cp.async.wait_group 0;\n");
        __syncthreads();
        int buf = kt & 1;
        if (kt + 1 < KT) {
            int nb = buf ^ 1;
            cp16(saw + nb * offA, aptr + (size_t)(kt + 1) * BK, asz);
            cp16(sbw + nb * offB, bptr + (size_t)(kt + 1) * BK * ldb, bsz);
            asm volatile("cp.async.commit_group;\n");
        }
        wmma::fragment<wmma::matrix_b, 16, 16, 16, __nv_bfloat16, wmma::row_major> fb[2];
        #pragma unroll
        for (int j = 0; j < 2; j++)
            wmma::load_matrix_sync(fb[j], &sB[buf][wn * 32 + j * 16], LDB_S);
        #pragma unroll
        for (int i = 0; i < 4; i++) {
            wmma::fragment<wmma::matrix_a, 16, 16, 16, __nv_bfloat16, wmma::row_major> fa;
            wmma::load_matrix_sync(fa, &sA[buf][(wm * 64 + i * 16) * BK], BK);
            #pragma unroll
            for (int j = 0; j < 2; j++)
                wmma::mma_sync(acc[i][j], fa, fb[j], acc[i][j]);
        }
    }

    // epilogue: per-warp smem staging, scalar guarded writes with fused bias+act
    float* sc = sC[warp];
    int r = lane >> 1;
    int cb = (lane & 1) << 4;
    #pragma unroll
    for (int i = 0; i < 4; i++) {
        wmma::store_matrix_sync(sc,      acc[i][0], LDC_S, wmma::mem_row_major);
        wmma::store_matrix_sync(sc + 16, acc[i][1], LDC_S, wmma::mem_row_major);
        __syncwarp();
        int row = bm0 + wm * 64 + i * 16 + r;
        if (row < M) {
            CT* cout = C + (size_t)row * ldc + ccol0;
            int col0 = bn0 + wn * 32 + cb;
            #pragma unroll
            for (int c = 0; c < 16; c++) {
                int col = col0 + c;
                if (col < N) {
                    float v = sc[r * LDC_S + cb + c];
                    if (bias) v += bias[col];
                    if (ACT == 1) v = tanhf(v);
                    else if (ACT == 2) v = v >= 0.f ? v : 1e-4f * v;
                    else if (ACT == 3) v = v >= 0.f ? v : 1e-3f * v;
                    if constexpr (sizeof(CT) == 2) cout[col] = __float2bfloat16(v);
                    else                           cout[col] = v;
                }
            }
        }
        __syncwarp();
    }
}

// ---------------- launch ----------------
extern "C" void kernel_launch(void* const* d_in, const int* in_sizes, int n_in,
                              void* d_out, int out_size) {
    const int *ei = 0, *et = 0, *tt = 0;
    const float *ent = 0, *rel = 0, *W = 0, *Wl = 0, *Wr = 0, *tw = 0, *tb = 0;
    const float *qw = 0, *qb = 0, *kw = 0, *kb = 0, *w1 = 0, *b1 = 0, *w2 = 0, *b2 = 0, *w3 = 0, *b3 = 0;
    int c40 = 0, c12800 = 0, c128 = 0, c512 = 0;
    for (int i = 0; i < n_in; i++) {
        const void* p = d_in[i];
        switch (in_sizes[i]) {
            case 1000000:  ei = (const int*)p; break;
            case 500000:   et = (const int*)p; break;
            case 262144:   tt = (const int*)p; break;
            case 20000000: ent = (const float*)p; break;
            case 94800:    rel = (const float*)p; break;
            case 40000:    if (c40 == 0) W = (const float*)p;
                           else if (c40 == 1) Wl = (const float*)p;
                           else Wr = (const float*)p;
                           c40++; break;
            case 20000:    tw = (const float*)p; break;
            case 100:      tb = (const float*)p; break;
            case 12800:    if (c12800 == 0) qw = (const float*)p; else kw = (const float*)p;
                           c12800++; break;
            case 128:      if (c128 == 0) qb = (const float*)p; else kb = (const float*)p;
                           c128++; break;
            case 1792000:  w1 = (const float*)p; break;
            case 2048:     b1 = (const float*)p; break;
            case 1048576:  w2 = (const float*)p; break;
            case 512:      if (c512 == 0) b2 = (const float*)p; else w3 = (const float*)p;
                           c512++; break;
            case 1:        b3 = (const float*)p; break;
        }
    }
    if (!ei || !et || !tt || !ent || !rel || !W || !Wl || !Wr || !tw || !tb ||
        !qw || !qb || !kw || !kb || !w1 || !b1 || !w2 || !b2 || !w3 || !b3) return;

    void *vX, *vWcat, *vAllent, *vCat, *vT2, *vHT, *vQKw, *vQK, *vBrel, *vW1b, *vH1, *vW2b, *vH2, *vB2, *vBQK;
    cudaGetSymbolAddress(&vX, g_X);
    cudaGetSymbolAddress(&vWcat, g_Wcat);
    cudaGetSymbolAddress(&vAllent, g_allent);
    cudaGetSymbolAddress(&vCat, g_cat);
    cudaGetSymbolAddress(&vT2, g_T2);
    cudaGetSymbolAddress(&vHT, g_HT);
    cudaGetSymbolAddress(&vQKw, g_QKw);
    cudaGetSymbolAddress(&vQK, g_QK);
    cudaGetSymbolAddress(&vBrel, g_Brel);
    cudaGetSymbolAddress(&vW1b, g_w1b);
    cudaGetSymbolAddress(&vH1, g_H1);
    cudaGetSymbolAddress(&vW2b, g_w2b);
    cudaGetSymbolAddress(&vH2, g_H2);
    cudaGetSymbolAddress(&vB2, g_bias2);
    cudaGetSymbolAddress(&vBQK, g_biasQK);

    __nv_bfloat16* X      = (__nv_bfloat16*)vX;
    __nv_bfloat16* WCAT   = (__nv_bfloat16*)vWcat;
    __nv_bfloat16* ALLENT = (__nv_bfloat16*)vAllent;
    __nv_bfloat16* CAT    = (__nv_bfloat16*)vCat;
    __nv_bfloat16* T2     = (__nv_bfloat16*)vT2;
    __nv_bfloat16* HT     = (__nv_bfloat16*)vHT;
    __nv_bfloat16* QKW    = (__nv_bfloat16*)vQKw;
    float*         QK     = (float*)vQK;
    __nv_bfloat16* BREL   = (__nv_bfloat16*)vBrel;
    __nv_bfloat16* W1B    = (__nv_bfloat16*)vW1b;
    __nv_bfloat16* H1     = (__nv_bfloat16*)vH1;
    __nv_bfloat16* W2B    = (__nv_bfloat16*)vW2b;
    __nv_bfloat16* H2     = (__nv_bfloat16*)vH2;
    float*         BIAS2  = (float*)vB2;
    float*         BIASQK = (float*)vBQK;

    const int T = 256;
    // 1) zero accumulators + degree
    k_zero<<<(5025000 + T - 1) / T, T>>>();
    // 2) edge scatter (segment sums hoisted out of the message GEMM)
    k_scatter<<<(NEDGE * 50 + T - 1) / T, T>>>(ei, et, ent, rel);
    // 3) weight prep (independent small kernels)
    k_f2b<<<(40000 + T - 1) / T, T>>>(WCAT, W, 40000);
    k_f2b<<<(40000 + T - 1) / T, T>>>(WCAT + 40000, Wl, 40000);
    k_f2b<<<(1048576 + T - 1) / T, T>>>(W2B, w2, 1048576);
    k_w1b<<<(880 * 2048 + T - 1) / T, T>>>(w1);
    k_T2<<<(400 * 200 + T - 1) / T, T>>>(tw);
    k_QKw<<<(200 * 256 + T - 1) / T, T>>>(qw, kw);
    k_bias<<<2, T>>>(tb, qb, kb);
    k_allrel<<<474, T>>>(rel, Wr);
    k_brel<<<(200 * 480 + T - 1) / T, T>>>();
    // 4) X = [agg*norm | ent] bf16
    k_buildX<<<(NE * 200 + T - 1) / T, T>>>(ent);
    // 5) all_ent = tanh(X @ [W;W_loop])       M=100000 N=200 K=400
    k_gemm<1, __nv_bfloat16><<<dim3(782, 2), T>>>(X, 400, WCAT, 200, ALLENT, 200, 0,
                                                  nullptr, NE, 200, 400);
    // 6) gather te pairs into cat[:, 0:400] (+ zero K-pad cols 875..879)
    k_gather<<<(NTEST * 64) / T, T>>>(tt);
    // 7) HT = [h_e|t_e] = cat[:,0:400] @ blockdiag(trans_w) + [tb|tb]   N=200 K=400
    k_gemm<0, __nv_bfloat16><<<dim3(1024, 2), T>>>(CAT, KCAT, T2, 200, HT, 200, 0,
                                                   BIAS2, NTEST, 200, 400);
    // 8) QK = HT @ blockdiag(q_w,k_w) + [q_b|k_b]   N=256 K=200 (fp32 out)
    k_gemm<0, float><<<dim3(1024, 2), T>>>(HT, 200, QKW, 256, QK, 256, 0,
                                           BIASQK, NTEST, 256, 200);
    // 9) atta -> cat[:, 400]
    k_atta<<<(NTEST * 32) / T, T>>>();
    // 10) relSim = HT @ [head_rel^T; -tail_rel^T] -> cat[:, 401:875]   N=474 K=200
    k_gemm<0, __nv_bfloat16><<<dim3(1024, 4), T>>>(HT, 200, BREL, 480, CAT, KCAT, 401,
                                                   nullptr, NTEST, NREL2, 200);
    // 11) H1 = lrelu(cat @ w1 + b1, 1e-4)      N=2048 K=880
    k_gemm<2, __nv_bfloat16><<<dim3(1024, 16), T>>>(CAT, KCAT, W1B, 2048, H1, 2048, 0,
                                                    b1, NTEST, 2048, 880);
    // 12) H2 = lrelu(H1 @ w2 + b2, 1e-3)       N=512 K=2048
    k_gemm<3, __nv_bfloat16><<<dim3(1024, 4), T>>>(H1, 2048, W2B, 512, H2, 512, 0,
                                                   b2, NTEST, 512, 2048);
    // 13) out = sigmoid(H2 @ w3 + b3)
    k_final<<<(NTEST * 32) / T, T>>>(w3, b3, (float*)d_out);
}